// round 10
// baseline (speedup 1.0000x reference)
#include <cuda_runtime.h>
#include <math.h>

#define BB 8
#define NN 16384
#define NP 2048
#define KS 32
#define SFULL (BB*NP*KS)   /* 524288 samples */
#define LDF 68

/* ------------------------------------------------------------------ */
/* Device scratch (no allocation allowed -> static globals)            */
/* ------------------------------------------------------------------ */
__device__ float  g_pointsT[BB*NN*64];      /* points transposed [b][n][64] */
__device__ float  g_ppsq[BB*NN];            /* |p|^2 per point              */
__device__ float  g_newxyz[BB*NP*3];        /* sampled centers [b][p][3]    */
__device__ int    g_knn[SFULL];             /* knn indices                  */
__device__ float  g_feat[(size_t)SFULL*LDF];/* feat [s][68]; reused as H1   */
__device__ float  g_h0[(size_t)SFULL*64];   /* H0 [s][64]                   */
__device__ double g_stats[256];             /* L0 sum/sq, L1 sum/sq         */
__device__ float  g_aff[256];               /* scale0,shift0,scale1,shift1  */

/* NVPTX SelectionDAG contraction of x^2+y^2+z^2 (bit-exact vs ref,
   confirmed by output-0 rel_err == 0):
   add(mul(x,x), mul(y,y)) folds FIRST operand -> fma(x,x, RN(y*y));
   trailing add folds the mul -> fma(z,z, fma(x,x, RN(y*y))).        */
__device__ __forceinline__ float sq3_dag(float x, float y, float z) {
    return __fmaf_rn(z, z, __fmaf_rn(x, x, __fmul_rn(y, y)));
}

__global__ void zero_stats_k() {
    int i = threadIdx.x;
    if (i < 256) g_stats[i] = 0.0;
}

/* points (B,64,N) -> g_pointsT (B,N,64) */
__global__ void transpose_k(const float* __restrict__ pts) {
    __shared__ float t[32][33];
    int b = blockIdx.z, n0 = blockIdx.x * 32, c0 = blockIdx.y * 32;
    int tx = threadIdx.x, ty = threadIdx.y;  /* 32 x 8 */
    const float* src = pts + (size_t)b * 64 * NN;
#pragma unroll
    for (int i = 0; i < 4; i++)
        t[ty + i * 8][tx] = src[(size_t)(c0 + ty + i * 8) * NN + n0 + tx];
    __syncthreads();
    float* dst = g_pointsT + (size_t)b * NN * 64;
#pragma unroll
    for (int i = 0; i < 4; i++)
        dst[(size_t)(n0 + ty + i * 8) * 64 + c0 + tx] = t[tx][ty + i * 8];
}

/* |p|^2 in DAG-contracted form */
__global__ void ppsq_k(const float* __restrict__ xyz) {
    int i = blockIdx.x * 256 + threadIdx.x;   /* < BB*NN */
    int b = i >> 14, n = i & (NN - 1);
    const float* x = xyz + (size_t)b * 3 * NN;
    g_ppsq[i] = sq3_dag(x[n], x[NN + n], x[2 * NN + n]);
}

/* ------------------------------------------------------------------ */
/* Furthest point sampling: one CTA per batch, xyz staged in smem.     */
/* BIT-EXACT vs reference (output-0 rel_err == 0). Do not change.      */
/* ------------------------------------------------------------------ */
__global__ __launch_bounds__(1024)
void fps_k(const float* __restrict__ xyz, float* __restrict__ out_newxyz) {
    extern __shared__ float sm[];
    float* sx = sm;
    float* sy = sm + NN;
    float* sz = sm + 2 * NN;
    float* s_v = sm + 3 * NN;                 /* 32 */
    int*   s_i = (int*)(sm + 3 * NN + 32);    /* 32 */
    int*   s_sel = (int*)(sm + 3 * NN + 64);

    int b = blockIdx.x, tid = threadIdx.x;
    const float* x = xyz + (size_t)b * 3 * NN;
    for (int i = tid; i < NN; i += 1024) {
        sx[i] = x[i]; sy[i] = x[NN + i]; sz[i] = x[2 * NN + i];
    }
    float dist[16];
#pragma unroll
    for (int j = 0; j < 16; j++) dist[j] = 1e10f;
    if (tid == 0) *s_sel = 0;
    __syncthreads();

    int lane = tid & 31, warp = tid >> 5;
    for (int it = 0; it < NP; it++) {
        int sel = *s_sel;
        float cx = sx[sel], cy = sy[sel], cz = sz[sel];
        if (tid == 0) {
            g_newxyz[(b * NP + it) * 3 + 0] = cx;
            g_newxyz[(b * NP + it) * 3 + 1] = cy;
            g_newxyz[(b * NP + it) * 3 + 2] = cz;
            out_newxyz[(size_t)b * 3 * NP + 0 * NP + it] = cx;
            out_newxyz[(size_t)b * 3 * NP + 1 * NP + it] = cy;
            out_newxyz[(size_t)b * 3 * NP + 2 * NP + it] = cz;
        }
        float bv = -1.0f; int bi = 0x7fffffff;
#pragma unroll
        for (int j = 0; j < 16; j++) {
            int n = tid + j * 1024;
            float dx = __fadd_rn(sx[n], -cx);
            float dy = __fadd_rn(sy[n], -cy);
            float dz = __fadd_rn(sz[n], -cz);
            float d = sq3_dag(dx, dy, dz);
            float dj = fminf(dist[j], d);
            dist[j] = dj;
            if (dj > bv) { bv = dj; bi = n; }   /* ascending n keeps first max */
        }
#pragma unroll
        for (int off = 16; off > 0; off >>= 1) {
            float ov = __shfl_down_sync(0xffffffffu, bv, off);
            int   oi = __shfl_down_sync(0xffffffffu, bi, off);
            if (ov > bv || (ov == bv && oi < bi)) { bv = ov; bi = oi; }
        }
        if (lane == 0) { s_v[warp] = bv; s_i[warp] = bi; }
        __syncthreads();
        if (tid < 32) {
            bv = s_v[tid]; bi = s_i[tid];
#pragma unroll
            for (int off = 16; off > 0; off >>= 1) {
                float ov = __shfl_down_sync(0xffffffffu, bv, off);
                int   oi = __shfl_down_sync(0xffffffffu, bi, off);
                if (ov > bv || (ov == bv && oi < bi)) { bv = ov; bi = oi; }
            }
            if (tid == 0) *s_sel = bi;
        }
        __syncthreads();
    }
}

/* ------------------------------------------------------------------ */
/* Brute-force KNN top-32: 1 thread per query, candidates via smem.    */
/* FULL f32: dot = ascending-k fma chain (matches cuBLAS f32 K=3),     */
/* dist = fadd(fma(-2,dot,qq), pp) (DAG form), qq/pp via sq3_dag.      */
/* Ties keep lower candidate index.                                    */
/* ------------------------------------------------------------------ */
__global__ __launch_bounds__(256)
void knn_k(const float* __restrict__ xyz) {
    __shared__ float scx[2048], scy[2048], scz[2048], scq[2048];
    int b = blockIdx.x >> 3;
    int p = (blockIdx.x & 7) * 256 + threadIdx.x;
    const float* x = xyz + (size_t)b * 3 * NN;
    float qx = g_newxyz[(b * NP + p) * 3 + 0];
    float qy = g_newxyz[(b * NP + p) * 3 + 1];
    float qz = g_newxyz[(b * NP + p) * 3 + 2];
    float qq = sq3_dag(qx, qy, qz);

    float kd[KS]; int ki[KS];
#pragma unroll
    for (int j = 0; j < KS; j++) { kd[j] = 3.0e38f; ki[j] = 0; }

    for (int c0 = 0; c0 < NN; c0 += 2048) {
        for (int i = threadIdx.x; i < 2048; i += 256) {
            scx[i] = x[c0 + i];
            scy[i] = x[NN + c0 + i];
            scz[i] = x[2 * NN + c0 + i];
            scq[i] = g_ppsq[b * NN + c0 + i];
        }
        __syncthreads();
        float worst = kd[KS - 1];
#pragma unroll 4
        for (int i = 0; i < 2048; i++) {
            float dot = __fmaf_rn(qz, scz[i], __fmaf_rn(qy, scy[i], __fmul_rn(qx, scx[i])));
            float d = __fadd_rn(__fmaf_rn(-2.0f, dot, qq), scq[i]);
            if (d < worst) {
                int pos = KS - 1;
                while (pos > 0 && kd[pos - 1] > d) {
                    kd[pos] = kd[pos - 1]; ki[pos] = ki[pos - 1]; pos--;
                }
                kd[pos] = d; ki[pos] = c0 + i;
                worst = kd[KS - 1];
            }
        }
        __syncthreads();
    }
    int base = (b * NP + p) * KS;
    for (int j = 0; j < KS; j++) g_knn[base + j] = ki[j];
}

/* ------------------------------------------------------------------ */
/* Build feat[s][68]: [0:3)=xyz-center, [3:67)=points row, [67]=pad.   */
/* ------------------------------------------------------------------ */
__global__ __launch_bounds__(256)
void feat_k(const float* __restrict__ xyz) {
    int s = blockIdx.x * 8 + (threadIdx.x >> 5);
    int lane = threadIdx.x & 31;
    int b = s >> 16;
    int p = (s >> 5) & (NP - 1);
    int i = g_knn[s];
    const float* pt = g_pointsT + ((size_t)b * NN + i) * 64;
    float* f = g_feat + (size_t)s * LDF;
    for (int c = lane; c < LDF; c += 32) {
        float v;
        if (c < 3)
            v = __fadd_rn(xyz[(size_t)b * 3 * NN + c * NN + i],
                          -g_newxyz[(b * NP + p) * 3 + c]);
        else if (c < 67)
            v = pt[c - 3];
        else
            v = 0.f;
        f[c] = v;
    }
}

/* ------------------------------------------------------------------ */
/* Fused 1x1-conv GEMM, FULL f32 (ascending-k fma chain per output —   */
/* same rounding as cuBLAS sgemm inner loop).                          */
/* INAFF : relu(scale*x+shift) applied to inputs while staging (BN).   */
/* STATS : per-out-channel sum/sumsq in double (for BN fold).          */
/* MAXPOOL: max over k=32 group + bias, scatter to (B,128,NP) output.  */
/* Conv biases b0/b1 cancel under training-mode BN (zeros anyway).     */
/* ------------------------------------------------------------------ */
template<int M, int KIN, int LDB, int SB, int TS, int TC,
         bool INAFF, bool STATS, bool MAXPOOL>
__global__ __launch_bounds__(256)
void gemm_k(const float* __restrict__ Wg, const float* __restrict__ Xg,
            float* __restrict__ Og, const float* __restrict__ bias,
            int affoff, int statoff)
{
    constexpr int NS  = SB / TS;       /* sample-threads */
    constexpr int WST = M + 4;
    constexpr int XST = SB + 4;
    __shared__ __align__(16) float Ws[KIN * WST];
    __shared__ __align__(16) float Xs[KIN * XST];
    int t = threadIdx.x;

    for (int idx = t; idx < M * KIN; idx += 256) {
        int m = idx / KIN, k = idx - m * KIN;
        Ws[k * WST + m] = Wg[idx];
    }
    size_t sbase = (size_t)blockIdx.x * SB;
    for (int idx = t; idx < SB * KIN; idx += 256) {
        int s = idx / KIN, k = idx - s * KIN;
        float v = Xg[(sbase + s) * (size_t)LDB + k];
        if (INAFF)
            v = fmaxf(fmaf(g_aff[affoff + k], v, g_aff[affoff + 64 + k]), 0.f);
        Xs[k * XST + s] = v;
    }
    __syncthreads();

    int s_idx = t % NS, c_idx = t / NS;
    int sj = s_idx * TS, cj = c_idx * TC;
    float acc[TS][TC];
#pragma unroll
    for (int i = 0; i < TS; i++)
#pragma unroll
        for (int j = 0; j < TC; j++) acc[i][j] = 0.f;

    for (int k = 0; k < KIN; k++) {
        float xs[TS], wv[TC];
#pragma unroll
        for (int i = 0; i < TS; i++) xs[i] = Xs[k * XST + sj + i];
#pragma unroll
        for (int j = 0; j < TC; j++) wv[j] = Ws[k * WST + cj + j];
#pragma unroll
        for (int i = 0; i < TS; i++)
#pragma unroll
            for (int j = 0; j < TC; j++)
                acc[i][j] = fmaf(xs[i], wv[j], acc[i][j]);
    }

    if (MAXPOOL) {
        int b = (int)(sbase >> 16);
        int p = (int)((sbase >> 5) & (NP - 1));
#pragma unroll
        for (int j = 0; j < TC; j++) {
            float m = acc[0][j];
#pragma unroll
            for (int i = 1; i < TS; i++) m = fmaxf(m, acc[i][j]);
#pragma unroll
            for (int off = NS / 2; off > 0; off >>= 1)
                m = fmaxf(m, __shfl_xor_sync(0xffffffffu, m, off));
            if (s_idx == 0)
                Og[(size_t)(b * 128 + cj + j) * NP + p] = m + bias[cj + j];
        }
    } else {
#pragma unroll
        for (int i = 0; i < TS; i++)
#pragma unroll
            for (int j = 0; j < TC; j++)
                Og[(sbase + sj + i) * 64 + cj + j] = acc[i][j];
    }

    if (STATS) {
#pragma unroll
        for (int j = 0; j < TC; j++) {
            double s1 = 0.0, s2 = 0.0;
#pragma unroll
            for (int i = 0; i < TS; i++) {
                double v = (double)acc[i][j]; s1 += v; s2 += v * v;
            }
#pragma unroll
            for (int off = NS / 2; off > 0; off >>= 1) {
                s1 += __shfl_xor_sync(0xffffffffu, s1, off);
                s2 += __shfl_xor_sync(0xffffffffu, s2, off);
            }
            if (s_idx == 0) {
                atomicAdd(&g_stats[statoff + cj + j], s1);
                atomicAdd(&g_stats[statoff + 64 + cj + j], s2);
            }
        }
    }
}

/* BN fold: scale = gamma/sqrt(var+eps), shift = beta - mean*scale */
__global__ void fold_k(const float* __restrict__ gamma, const float* __restrict__ beta,
                       int statoff, int affoff) {
    int c = threadIdx.x;
    if (c >= 64) return;
    double n = (double)SFULL;
    double mean = g_stats[statoff + c] / n;
    double var = g_stats[statoff + 64 + c] / n - mean * mean;
    double sc = (double)gamma[c] / sqrt(var + 1e-5);
    g_aff[affoff + c] = (float)sc;
    g_aff[affoff + 64 + c] = (float)((double)beta[c] - mean * sc);
}

/* ------------------------------------------------------------------ */
extern "C" void kernel_launch(void* const* d_in, const int* in_sizes, int n_in,
                              void* d_out, int out_size) {
    const float* xyz    = (const float*)d_in[0];
    const float* points = (const float*)d_in[1];
    const float* W0  = (const float*)d_in[2];
    const float* g0  = (const float*)d_in[4];
    const float* bt0 = (const float*)d_in[5];
    const float* W1  = (const float*)d_in[6];
    const float* g1  = (const float*)d_in[8];
    const float* bt1 = (const float*)d_in[9];
    const float* W2  = (const float*)d_in[10];
    const float* b2  = (const float*)d_in[11];
    float* out    = (float*)d_out;
    float* out_np = out + BB * 3 * NP;     /* new_points after new_xyz */

    void* p_feat = 0; void* p_h0 = 0;
    cudaGetSymbolAddress(&p_feat, g_feat);
    cudaGetSymbolAddress(&p_h0, g_h0);
    float* feat = (float*)p_feat;
    float* h0   = (float*)p_h0;

    const int fps_smem = 3 * NN * 4 + 1024;
    cudaFuncSetAttribute(fps_k, cudaFuncAttributeMaxDynamicSharedMemorySize, fps_smem);

    zero_stats_k<<<1, 256>>>();
    transpose_k<<<dim3(NN / 32, 2, BB), dim3(32, 8)>>>(points);
    ppsq_k<<<BB * NN / 256, 256>>>(xyz);
    fps_k<<<BB, 1024, fps_smem>>>(xyz, out);
    knn_k<<<BB * 8, 256>>>(xyz);
    feat_k<<<SFULL / 8, 256>>>(xyz);

    /* L0: 67 -> 64, raw output + stats */
    gemm_k<64, 67, 68, 64, 4, 4, false, true, false>
        <<<SFULL / 64, 256>>>(W0, feat, h0, nullptr, 0, 0);
    fold_k<<<1, 64>>>(g0, bt0, 0, 0);
    /* L1: relu(BN(h0)) -> 64, raw output + stats (h1 stored into feat) */
    gemm_k<64, 64, 64, 64, 4, 4, true, true, false>
        <<<SFULL / 64, 256>>>(W1, h0, feat, nullptr, 0, 128);
    fold_k<<<1, 64>>>(g1, bt1, 128, 128);
    /* L2: relu(BN(h1)) -> 128, fused max over k, +b2 */
    gemm_k<128, 64, 64, 32, 2, 8, true, false, true>
        <<<SFULL / 32, 256>>>(W2, feat, out_np, b2, 128, 0);
}

// round 11
// speedup vs baseline: 1.6102x; 1.6102x over previous
#include <cuda_runtime.h>
#include <math.h>

#define BB 8
#define NN 16384
#define NP 2048
#define KS 32
#define SFULL (BB*NP*KS)   /* 524288 samples */
#define LDF 68

/* ------------------------------------------------------------------ */
/* Device scratch (no allocation allowed -> static globals)            */
/* ------------------------------------------------------------------ */
__device__ float  g_pointsT[BB*NN*64];      /* points transposed [b][n][64] */
__device__ float  g_newxyz[BB*NP*3];        /* sampled centers [b][p][3]    */
__device__ int    g_knn[SFULL];             /* knn indices                  */
__device__ float  g_feat[(size_t)SFULL*LDF];/* feat [s][68]; reused as H1   */
__device__ float  g_h0[(size_t)SFULL*64];   /* H0 [s][64]                   */
__device__ double g_stats[256];             /* L0 sum/sq, L1 sum/sq         */
__device__ float  g_aff[256];               /* scale0,shift0,scale1,shift1  */

/* NVPTX SelectionDAG contraction of x^2+y^2+z^2 — BIT-EXACT vs ref.   */
__device__ __forceinline__ float sq3_dag(float x, float y, float z) {
    return __fmaf_rn(z, z, __fmaf_rn(x, x, __fmul_rn(y, y)));
}

__device__ __forceinline__ unsigned smem_u32(const void* p) {
    return (unsigned)__cvta_generic_to_shared(p);
}
__device__ __forceinline__ void dsmem_st_f32(unsigned laddr, unsigned peer, float v) {
    unsigned r;
    asm volatile("mapa.shared::cluster.u32 %0, %1, %2;" : "=r"(r) : "r"(laddr), "r"(peer));
    asm volatile("st.shared::cluster.f32 [%0], %1;" :: "r"(r), "f"(v));
}
__device__ __forceinline__ void dsmem_st_b32(unsigned laddr, unsigned peer, int v) {
    unsigned r;
    asm volatile("mapa.shared::cluster.u32 %0, %1, %2;" : "=r"(r) : "r"(laddr), "r"(peer));
    asm volatile("st.shared::cluster.b32 [%0], %1;" :: "r"(r), "r"(v));
}
#define CLUSTER_SYNC() do { \
    asm volatile("barrier.cluster.arrive.aligned;" ::: "memory"); \
    asm volatile("barrier.cluster.wait.aligned;"   ::: "memory"); \
} while (0)

__global__ void zero_stats_k() {
    int i = threadIdx.x;
    if (i < 256) g_stats[i] = 0.0;
}

/* points (B,64,N) -> g_pointsT (B,N,64) */
__global__ void transpose_k(const float* __restrict__ pts) {
    __shared__ float t[32][33];
    int b = blockIdx.z, n0 = blockIdx.x * 32, c0 = blockIdx.y * 32;
    int tx = threadIdx.x, ty = threadIdx.y;  /* 32 x 8 */
    const float* src = pts + (size_t)b * 64 * NN;
#pragma unroll
    for (int i = 0; i < 4; i++)
        t[ty + i * 8][tx] = src[(size_t)(c0 + ty + i * 8) * NN + n0 + tx];
    __syncthreads();
    float* dst = g_pointsT + (size_t)b * NN * 64;
#pragma unroll
    for (int i = 0; i < 4; i++)
        dst[(size_t)(n0 + ty + i * 8) * 64 + c0 + tx] = t[tx][ty + i * 8];
}

/* ------------------------------------------------------------------ */
/* FPS, cluster-2 per batch: grid=16, 2 CTAs share one batch.          */
/* Each CTA holds 8192 points in REGISTERS (8/thread). Selection math  */
/* (sq3_dag + f32 min + first-max argmax) is unchanged -> bit-exact:   */
/* (max val, min idx) is associative, so the 2-CTA re-partition of the */
/* reduction cannot change the selected index sequence.                */
/* Cross-CTA exchange: parity-double-buffered DSMEM mailbox + one      */
/* barrier.cluster per iteration.                                      */
/* ------------------------------------------------------------------ */
__global__ __launch_bounds__(1024, 1) __cluster_dims__(2, 1, 1)
void fps_k(const float* __restrict__ xyz, float* __restrict__ out_newxyz) {
    __shared__ float s_rv[32], s_rx[32], s_ry[32], s_rz[32];
    __shared__ int   s_ri[32];
    __shared__ float m_v[2][2], m_x[2][2], m_y[2][2], m_z[2][2];
    __shared__ int   m_i[2][2];

    int b = blockIdx.x >> 1;
    unsigned rank;
    asm("mov.u32 %0, %%cluster_ctarank;" : "=r"(rank));
    int tid = threadIdx.x;
    const float* x = xyz + (size_t)b * 3 * NN;
    int base_g = (int)rank * 8192;

    float px[8], py[8], pz[8], dist[8];
#pragma unroll
    for (int j = 0; j < 8; j++) {
        int g = base_g + tid + j * 1024;
        px[j] = x[g]; py[j] = x[NN + g]; pz[j] = x[2 * NN + g];
        dist[j] = 1e10f;
    }
    float cx = x[0], cy = x[NN], cz = x[2 * NN];   /* initial centroid = pt 0 */

    int lane = tid & 31, warp = tid >> 5;

    for (int it = 0; it < NP; it++) {
        if (rank == 0 && tid == 0) {
            g_newxyz[(b * NP + it) * 3 + 0] = cx;
            g_newxyz[(b * NP + it) * 3 + 1] = cy;
            g_newxyz[(b * NP + it) * 3 + 2] = cz;
            out_newxyz[(size_t)b * 3 * NP + 0 * NP + it] = cx;
            out_newxyz[(size_t)b * 3 * NP + 1 * NP + it] = cy;
            out_newxyz[(size_t)b * 3 * NP + 2 * NP + it] = cz;
        }
        float bv = -1.0f, bx = 0.f, by = 0.f, bz = 0.f;
        int bi = 0x7fffffff;
#pragma unroll
        for (int j = 0; j < 8; j++) {
            float dx = __fadd_rn(px[j], -cx);
            float dy = __fadd_rn(py[j], -cy);
            float dz = __fadd_rn(pz[j], -cz);
            float d = sq3_dag(dx, dy, dz);
            float dj = fminf(dist[j], d);
            dist[j] = dj;
            if (dj > bv) {                     /* ascending idx: first max */
                bv = dj; bi = base_g + tid + j * 1024;
                bx = px[j]; by = py[j]; bz = pz[j];
            }
        }
#pragma unroll
        for (int off = 16; off > 0; off >>= 1) {
            float ov = __shfl_down_sync(0xffffffffu, bv, off);
            int   oi = __shfl_down_sync(0xffffffffu, bi, off);
            float ox = __shfl_down_sync(0xffffffffu, bx, off);
            float oy = __shfl_down_sync(0xffffffffu, by, off);
            float oz = __shfl_down_sync(0xffffffffu, bz, off);
            if (ov > bv || (ov == bv && oi < bi)) {
                bv = ov; bi = oi; bx = ox; by = oy; bz = oz;
            }
        }
        if (lane == 0) {
            s_rv[warp] = bv; s_ri[warp] = bi;
            s_rx[warp] = bx; s_ry[warp] = by; s_rz[warp] = bz;
        }
        __syncthreads();
        if (warp == 0) {
            bv = s_rv[lane]; bi = s_ri[lane];
            bx = s_rx[lane]; by = s_ry[lane]; bz = s_rz[lane];
#pragma unroll
            for (int off = 16; off > 0; off >>= 1) {
                float ov = __shfl_down_sync(0xffffffffu, bv, off);
                int   oi = __shfl_down_sync(0xffffffffu, bi, off);
                float ox = __shfl_down_sync(0xffffffffu, bx, off);
                float oy = __shfl_down_sync(0xffffffffu, by, off);
                float oz = __shfl_down_sync(0xffffffffu, bz, off);
                if (ov > bv || (ov == bv && oi < bi)) {
                    bv = ov; bi = oi; bx = ox; by = oy; bz = oz;
                }
            }
            if (lane == 0) {
                int par = it & 1;
                m_v[par][rank] = bv; m_i[par][rank] = bi;
                m_x[par][rank] = bx; m_y[par][rank] = by; m_z[par][rank] = bz;
                unsigned peer = rank ^ 1u;
                dsmem_st_f32(smem_u32(&m_v[par][rank]), peer, bv);
                dsmem_st_b32(smem_u32(&m_i[par][rank]), peer, bi);
                dsmem_st_f32(smem_u32(&m_x[par][rank]), peer, bx);
                dsmem_st_f32(smem_u32(&m_y[par][rank]), peer, by);
                dsmem_st_f32(smem_u32(&m_z[par][rank]), peer, bz);
            }
        }
        CLUSTER_SYNC();
        {
            int par = it & 1;
            float v0 = m_v[par][0], v1 = m_v[par][1];
            int   i0 = m_i[par][0], i1 = m_i[par][1];
            bool take1 = (v1 > v0) || (v1 == v0 && i1 < i0);
            cx = take1 ? m_x[par][1] : m_x[par][0];
            cy = take1 ? m_y[par][1] : m_y[par][0];
            cz = take1 ? m_z[par][1] : m_z[par][0];
        }
    }
}

/* ------------------------------------------------------------------ */
/* KNN top-32, 8-way candidate split: CTA = 32 queries x 8 warps.      */
/* All 16384 candidates staged in smem (192KB); warp = one 2048-range, */
/* lane = one query (candidate reads are warp-broadcast, conflict-free)*/
/* Distance math identical to the passing version (pp recomputed with  */
/* sq3_dag == old g_ppsq). 8 sorted top-32 lists merged per query with */
/* (d, idx)-lexicographic order == previous global tie semantics.      */
/* ------------------------------------------------------------------ */
__global__ __launch_bounds__(256)
void knn_k(const float* __restrict__ xyz) {
    extern __shared__ float ks[];
    float* scx = ks;
    float* scy = ks + NN;
    float* scz = ks + 2 * NN;

    int qg = blockIdx.x * 32;          /* 512 blocks cover 16384 queries */
    int b = qg >> 11;                  /* 2048 queries per batch          */
    const float* x = xyz + (size_t)b * 3 * NN;
    int tid = threadIdx.x;

    for (int i = tid; i < NN; i += 256) {
        scx[i] = x[i];
        scy[i] = x[NN + i];
        scz[i] = x[2 * NN + i];
    }
    __syncthreads();

    int q = tid & 31, s = tid >> 5;    /* lane = query, warp = split */
    int qi = qg + q;
    float qx = g_newxyz[qi * 3 + 0];
    float qy = g_newxyz[qi * 3 + 1];
    float qz = g_newxyz[qi * 3 + 2];
    float qq = sq3_dag(qx, qy, qz);

    float kd[KS]; int ki[KS];
#pragma unroll
    for (int j = 0; j < KS; j++) { kd[j] = 3.0e38f; ki[j] = 0; }

    int c0 = s * 2048;
    float worst = kd[KS - 1];
#pragma unroll 4
    for (int i = 0; i < 2048; i++) {
        int c = c0 + i;
        float cxv = scx[c], cyv = scy[c], czv = scz[c];
        float pp = sq3_dag(cxv, cyv, czv);
        float dot = __fmaf_rn(qz, czv, __fmaf_rn(qy, cyv, __fmul_rn(qx, cxv)));
        float d = __fadd_rn(__fmaf_rn(-2.0f, dot, qq), pp);
        if (d < worst) {
            int pos = KS - 1;
            while (pos > 0 && kd[pos - 1] > d) {
                kd[pos] = kd[pos - 1]; ki[pos] = ki[pos - 1]; pos--;
            }
            kd[pos] = d; ki[pos] = c;
            worst = kd[KS - 1];
        }
    }
    __syncthreads();                   /* before smem reuse */

    float* md = ks;                    /* 32q x 8s x 32 floats = 8192 */
    int*   mi = (int*)(ks + 8192);
    for (int r = 0; r < KS; r++) {
        md[(q * 8 + s) * 32 + r] = kd[r];
        mi[(q * 8 + s) * 32 + r] = ki[r];
    }
    __syncthreads();

    if (tid < 32) {                    /* one merger thread per query */
        int p8[8] = {0, 0, 0, 0, 0, 0, 0, 0};
        int base = (qg + tid) * KS;
        for (int r = 0; r < KS; r++) {
            float bd = 3.5e38f; int bidx = 0x7fffffff; int bsel = 0;
#pragma unroll
            for (int s2 = 0; s2 < 8; s2++) {
                float d2 = md[(tid * 8 + s2) * 32 + p8[s2]];
                int   i2 = mi[(tid * 8 + s2) * 32 + p8[s2]];
                if (d2 < bd || (d2 == bd && i2 < bidx)) { bd = d2; bidx = i2; bsel = s2; }
            }
            g_knn[base + r] = bidx;
            p8[bsel]++;
        }
    }
}

/* ------------------------------------------------------------------ */
/* Build feat[s][68]: [0:3)=xyz-center, [3:67)=points row, [67]=pad.   */
/* ------------------------------------------------------------------ */
__global__ __launch_bounds__(256)
void feat_k(const float* __restrict__ xyz) {
    int s = blockIdx.x * 8 + (threadIdx.x >> 5);
    int lane = threadIdx.x & 31;
    int b = s >> 16;
    int p = (s >> 5) & (NP - 1);
    int i = g_knn[s];
    const float* pt = g_pointsT + ((size_t)b * NN + i) * 64;
    float* f = g_feat + (size_t)s * LDF;
    for (int c = lane; c < LDF; c += 32) {
        float v;
        if (c < 3)
            v = __fadd_rn(xyz[(size_t)b * 3 * NN + c * NN + i],
                          -g_newxyz[(b * NP + p) * 3 + c]);
        else if (c < 67)
            v = pt[c - 3];
        else
            v = 0.f;
        f[c] = v;
    }
}

/* ------------------------------------------------------------------ */
/* Fused 1x1-conv GEMM, full f32 (proven: rel_err 1.3e-7).             */
/* ------------------------------------------------------------------ */
template<int M, int KIN, int LDB, int SB, int TS, int TC,
         bool INAFF, bool STATS, bool MAXPOOL>
__global__ __launch_bounds__(256)
void gemm_k(const float* __restrict__ Wg, const float* __restrict__ Xg,
            float* __restrict__ Og, const float* __restrict__ bias,
            int affoff, int statoff)
{
    constexpr int NS  = SB / TS;       /* sample-threads */
    constexpr int WST = M + 4;
    constexpr int XST = SB + 4;
    __shared__ __align__(16) float Ws[KIN * WST];
    __shared__ __align__(16) float Xs[KIN * XST];
    int t = threadIdx.x;

    for (int idx = t; idx < M * KIN; idx += 256) {
        int m = idx / KIN, k = idx - m * KIN;
        Ws[k * WST + m] = Wg[idx];
    }
    size_t sbase = (size_t)blockIdx.x * SB;
    for (int idx = t; idx < SB * KIN; idx += 256) {
        int s = idx / KIN, k = idx - s * KIN;
        float v = Xg[(sbase + s) * (size_t)LDB + k];
        if (INAFF)
            v = fmaxf(fmaf(g_aff[affoff + k], v, g_aff[affoff + 64 + k]), 0.f);
        Xs[k * XST + s] = v;
    }
    __syncthreads();

    int s_idx = t % NS, c_idx = t / NS;
    int sj = s_idx * TS, cj = c_idx * TC;
    float acc[TS][TC];
#pragma unroll
    for (int i = 0; i < TS; i++)
#pragma unroll
        for (int j = 0; j < TC; j++) acc[i][j] = 0.f;

    for (int k = 0; k < KIN; k++) {
        float xs[TS], wv[TC];
#pragma unroll
        for (int i = 0; i < TS; i++) xs[i] = Xs[k * XST + sj + i];
#pragma unroll
        for (int j = 0; j < TC; j++) wv[j] = Ws[k * WST + cj + j];
#pragma unroll
        for (int i = 0; i < TS; i++)
#pragma unroll
            for (int j = 0; j < TC; j++)
                acc[i][j] = fmaf(xs[i], wv[j], acc[i][j]);
    }

    if (MAXPOOL) {
        int b = (int)(sbase >> 16);
        int p = (int)((sbase >> 5) & (NP - 1));
#pragma unroll
        for (int j = 0; j < TC; j++) {
            float m = acc[0][j];
#pragma unroll
            for (int i = 1; i < TS; i++) m = fmaxf(m, acc[i][j]);
#pragma unroll
            for (int off = NS / 2; off > 0; off >>= 1)
                m = fmaxf(m, __shfl_xor_sync(0xffffffffu, m, off));
            if (s_idx == 0)
                Og[(size_t)(b * 128 + cj + j) * NP + p] = m + bias[cj + j];
        }
    } else {
#pragma unroll
        for (int i = 0; i < TS; i++)
#pragma unroll
            for (int j = 0; j < TC; j++)
                Og[(sbase + sj + i) * 64 + cj + j] = acc[i][j];
    }

    if (STATS) {
#pragma unroll
        for (int j = 0; j < TC; j++) {
            double s1 = 0.0, s2 = 0.0;
#pragma unroll
            for (int i = 0; i < TS; i++) {
                double v = (double)acc[i][j]; s1 += v; s2 += v * v;
            }
#pragma unroll
            for (int off = NS / 2; off > 0; off >>= 1) {
                s1 += __shfl_xor_sync(0xffffffffu, s1, off);
                s2 += __shfl_xor_sync(0xffffffffu, s2, off);
            }
            if (s_idx == 0) {
                atomicAdd(&g_stats[statoff + cj + j], s1);
                atomicAdd(&g_stats[statoff + 64 + cj + j], s2);
            }
        }
    }
}

/* BN fold: scale = gamma/sqrt(var+eps), shift = beta - mean*scale */
__global__ void fold_k(const float* __restrict__ gamma, const float* __restrict__ beta,
                       int statoff, int affoff) {
    int c = threadIdx.x;
    if (c >= 64) return;
    double n = (double)SFULL;
    double mean = g_stats[statoff + c] / n;
    double var = g_stats[statoff + 64 + c] / n - mean * mean;
    double sc = (double)gamma[c] / sqrt(var + 1e-5);
    g_aff[affoff + c] = (float)sc;
    g_aff[affoff + 64 + c] = (float)((double)beta[c] - mean * sc);
}

/* ------------------------------------------------------------------ */
extern "C" void kernel_launch(void* const* d_in, const int* in_sizes, int n_in,
                              void* d_out, int out_size) {
    const float* xyz    = (const float*)d_in[0];
    const float* points = (const float*)d_in[1];
    const float* W0  = (const float*)d_in[2];
    const float* g0  = (const float*)d_in[4];
    const float* bt0 = (const float*)d_in[5];
    const float* W1  = (const float*)d_in[6];
    const float* g1  = (const float*)d_in[8];
    const float* bt1 = (const float*)d_in[9];
    const float* W2  = (const float*)d_in[10];
    const float* b2  = (const float*)d_in[11];
    float* out    = (float*)d_out;
    float* out_np = out + BB * 3 * NP;     /* new_points after new_xyz */

    void* p_feat = 0; void* p_h0 = 0;
    cudaGetSymbolAddress(&p_feat, g_feat);
    cudaGetSymbolAddress(&p_h0, g_h0);
    float* feat = (float*)p_feat;
    float* h0   = (float*)p_h0;

    const int knn_smem = 3 * NN * 4;   /* 192KB */
    cudaFuncSetAttribute(knn_k, cudaFuncAttributeMaxDynamicSharedMemorySize, knn_smem);

    zero_stats_k<<<1, 256>>>();
    transpose_k<<<dim3(NN / 32, 2, BB), dim3(32, 8)>>>(points);
    fps_k<<<BB * 2, 1024>>>(xyz, out);            /* cluster-2 per batch */
    knn_k<<<512, 256, knn_smem>>>(xyz);
    feat_k<<<SFULL / 8, 256>>>(xyz);

    /* L0: 67 -> 64, raw output + stats */
    gemm_k<64, 67, 68, 64, 4, 4, false, true, false>
        <<<SFULL / 64, 256>>>(W0, feat, h0, nullptr, 0, 0);
    fold_k<<<1, 64>>>(g0, bt0, 0, 0);
    /* L1: relu(BN(h0)) -> 64, raw output + stats (h1 stored into feat) */
    gemm_k<64, 64, 64, 64, 4, 4, true, true, false>
        <<<SFULL / 64, 256>>>(W1, h0, feat, nullptr, 0, 128);
    fold_k<<<1, 64>>>(g1, bt1, 128, 128);
    /* L2: relu(BN(h1)) -> 128, fused max over k, +b2 */
    gemm_k<128, 64, 64, 32, 2, 8, true, false, true>
        <<<SFULL / 32, 256>>>(W2, feat, out_np, b2, 128, 0);
}

// round 12
// speedup vs baseline: 1.6196x; 1.0059x over previous
#include <cuda_runtime.h>
#include <math.h>

#define BB 8
#define NN 16384
#define NP 2048
#define KS 32
#define SFULL (BB*NP*KS)   /* 524288 samples */
#define LDF 68
#define CL 8               /* fps cluster size */

/* ------------------------------------------------------------------ */
/* Device scratch (no allocation allowed -> static globals)            */
/* ------------------------------------------------------------------ */
__device__ float  g_pointsT[BB*NN*64];      /* points transposed [b][n][64] */
__device__ float  g_newxyz[BB*NP*3];        /* sampled centers [b][p][3]    */
__device__ int    g_knn[SFULL];             /* knn indices                  */
__device__ float  g_feat[(size_t)SFULL*LDF];/* feat [s][68]; reused as H1   */
__device__ float  g_h0[(size_t)SFULL*64];   /* H0 [s][64]                   */
__device__ double g_stats[256];             /* L0 sum/sq, L1 sum/sq         */
__device__ float  g_aff[256];               /* scale0,shift0,scale1,shift1  */

/* NVPTX SelectionDAG contraction of x^2+y^2+z^2 — BIT-EXACT vs ref.   */
__device__ __forceinline__ float sq3_dag(float x, float y, float z) {
    return __fmaf_rn(z, z, __fmaf_rn(x, x, __fmul_rn(y, y)));
}

__device__ __forceinline__ unsigned smem_u32(const void* p) {
    return (unsigned)__cvta_generic_to_shared(p);
}
__device__ __forceinline__ unsigned mapa_u32(unsigned laddr, unsigned peer) {
    unsigned r;
    asm volatile("mapa.shared::cluster.u32 %0, %1, %2;" : "=r"(r) : "r"(laddr), "r"(peer));
    return r;
}
/* remote (cluster) weak store */
__device__ __forceinline__ void st_clu(unsigned a, int v) {
    asm volatile("st.shared::cluster.b32 [%0], %1;" :: "r"(a), "r"(v) : "memory");
}
/* remote (cluster) release store — publishes prior payload stores */
__device__ __forceinline__ void st_rel_clu(unsigned a, int v) {
    asm volatile("st.release.cluster.shared::cluster.b32 [%0], %1;" :: "r"(a), "r"(v) : "memory");
}
/* local acquire load, cluster scope (reads peer-written smem) */
__device__ __forceinline__ int ld_acq_clu(unsigned a) {
    int v;
    asm volatile("ld.acquire.cluster.shared::cta.b32 %0, [%1];" : "=r"(v) : "r"(a) : "memory");
    return v;
}
/* cta-scope release/acquire for intra-CTA warp mailbox */
__device__ __forceinline__ void st_rel_cta(unsigned a, int v) {
    asm volatile("st.release.cta.shared::cta.b32 [%0], %1;" :: "r"(a), "r"(v) : "memory");
}
__device__ __forceinline__ int ld_acq_cta(unsigned a) {
    int v;
    asm volatile("ld.acquire.cta.shared::cta.b32 %0, [%1];" : "=r"(v) : "r"(a) : "memory");
    return v;
}
#define CLUSTER_SYNC() do { \
    asm volatile("barrier.cluster.arrive.aligned;" ::: "memory"); \
    asm volatile("barrier.cluster.wait.aligned;"   ::: "memory"); \
} while (0)

__global__ void zero_stats_k() {
    int i = threadIdx.x;
    if (i < 256) g_stats[i] = 0.0;
}

/* points (B,64,N) -> g_pointsT (B,N,64) */
__global__ void transpose_k(const float* __restrict__ pts) {
    __shared__ float t[32][33];
    int b = blockIdx.z, n0 = blockIdx.x * 32, c0 = blockIdx.y * 32;
    int tx = threadIdx.x, ty = threadIdx.y;  /* 32 x 8 */
    const float* src = pts + (size_t)b * 64 * NN;
#pragma unroll
    for (int i = 0; i < 4; i++)
        t[ty + i * 8][tx] = src[(size_t)(c0 + ty + i * 8) * NN + n0 + tx];
    __syncthreads();
    float* dst = g_pointsT + (size_t)b * NN * 64;
#pragma unroll
    for (int i = 0; i < 4; i++)
        dst[(size_t)(n0 + ty + i * 8) * 64 + c0 + tx] = t[tx][ty + i * 8];
}

/* ------------------------------------------------------------------ */
/* FPS, cluster-8 per batch, SYNC-FREE iteration loop.                 */
/* 8 CTAs x 256 threads; 8 pts/thread in registers. Selection math     */
/* (sq3_dag, f32 min, (max v, min idx)) unchanged -> bit-exact.        */
/* Exchange via parity-double-buffered mailboxes with tag=it freshness */
/* (release/acquire); data deps bound skew so no barriers in the loop. */
/* Mailbox slot layout [par][slot][8]: 0=tag 1=v 2=idx 3=x 4=y 5=z.    */
/* ------------------------------------------------------------------ */
__global__ __launch_bounds__(256, 1) __cluster_dims__(CL, 1, 1)
void fps_k(const float* __restrict__ xyz, float* __restrict__ out_newxyz) {
    __shared__ int wm[2][8][8];   /* warp -> CTA mailbox   */
    __shared__ int gm[2][8][8];   /* cluster mailbox       */

    int b = blockIdx.x / CL;
    unsigned rank;
    asm("mov.u32 %0, %%cluster_ctarank;" : "=r"(rank));
    int tid = threadIdx.x, lane = tid & 31, warp = tid >> 5;
    const float* x = xyz + (size_t)b * 3 * NN;
    int base_g = (int)rank * 2048;

    float px[8], py[8], pz[8], dist[8];
#pragma unroll
    for (int j = 0; j < 8; j++) {
        int g = base_g + tid + j * 256;
        px[j] = x[g]; py[j] = x[NN + g]; pz[j] = x[2 * NN + g];
        dist[j] = 1e10f;
    }
    /* init tags to -1, then one-time cluster barrier */
    if (tid < 16)      wm[tid >> 3][tid & 7][0] = -1;
    else if (tid < 32) gm[(tid >> 3) & 1][tid & 7][0] = -1;
    __syncthreads();
    CLUSTER_SYNC();

    /* peer mailbox base for lanes 0..7 of warp0 (publish fan-out) */
    unsigned gm_local = smem_u32(&gm[0][0][0]);
    unsigned peer_gm = mapa_u32(gm_local, (unsigned)(lane & 7));

    float cx = x[0], cy = x[NN], cz = x[2 * NN];   /* centroid 0 = pt 0 */

    for (int it = 0; it < NP; it++) {
        if (rank == 0 && tid == 0) {
            g_newxyz[(b * NP + it) * 3 + 0] = cx;
            g_newxyz[(b * NP + it) * 3 + 1] = cy;
            g_newxyz[(b * NP + it) * 3 + 2] = cz;
            out_newxyz[(size_t)b * 3 * NP + 0 * NP + it] = cx;
            out_newxyz[(size_t)b * 3 * NP + 1 * NP + it] = cy;
            out_newxyz[(size_t)b * 3 * NP + 2 * NP + it] = cz;
        }
        int par = it & 1;

        /* local 8-point argmax (bit-exact update math) */
        float bv = -1.0f, bx = 0.f, by = 0.f, bz = 0.f;
        int bi = 0x7fffffff;
#pragma unroll
        for (int j = 0; j < 8; j++) {
            float dx = __fadd_rn(px[j], -cx);
            float dy = __fadd_rn(py[j], -cy);
            float dz = __fadd_rn(pz[j], -cz);
            float d = sq3_dag(dx, dy, dz);
            float dj = fminf(dist[j], d);
            dist[j] = dj;
            if (dj > bv) {                     /* ascending idx: first max */
                bv = dj; bi = base_g + tid + j * 256;
                bx = px[j]; by = py[j]; bz = pz[j];
            }
        }
        /* warp reduce (carry payload) */
#pragma unroll
        for (int off = 16; off > 0; off >>= 1) {
            float ov = __shfl_down_sync(0xffffffffu, bv, off);
            int   oi = __shfl_down_sync(0xffffffffu, bi, off);
            float ox = __shfl_down_sync(0xffffffffu, bx, off);
            float oy = __shfl_down_sync(0xffffffffu, by, off);
            float oz = __shfl_down_sync(0xffffffffu, bz, off);
            if (ov > bv || (ov == bv && oi < bi)) {
                bv = ov; bi = oi; bx = ox; by = oy; bz = oz;
            }
        }
        if (lane == 0) {          /* publish warp partial to CTA mailbox */
            wm[par][warp][1] = __float_as_int(bv);
            wm[par][warp][2] = bi;
            wm[par][warp][3] = __float_as_int(bx);
            wm[par][warp][4] = __float_as_int(by);
            wm[par][warp][5] = __float_as_int(bz);
            st_rel_cta(smem_u32(&wm[par][warp][0]), it);
        }
        /* warp0: gather 8 warp partials, reduce, publish to 8 CTAs */
        if (warp == 0 && lane < 8) {
            unsigned ta = smem_u32(&wm[par][lane][0]);
            while (ld_acq_cta(ta) != it) {}
            float v = __int_as_float(wm[par][lane][1]);
            int   i = wm[par][lane][2];
            float xx = __int_as_float(wm[par][lane][3]);
            float yy = __int_as_float(wm[par][lane][4]);
            float zz = __int_as_float(wm[par][lane][5]);
#pragma unroll
            for (int off = 4; off > 0; off >>= 1) {
                float ov = __shfl_down_sync(0x000000ffu, v, off, 8);
                int   oi = __shfl_down_sync(0x000000ffu, i, off, 8);
                float ox = __shfl_down_sync(0x000000ffu, xx, off, 8);
                float oy = __shfl_down_sync(0x000000ffu, yy, off, 8);
                float oz = __shfl_down_sync(0x000000ffu, zz, off, 8);
                if (ov > v || (ov == v && oi < i)) {
                    v = ov; i = oi; xx = ox; yy = oy; zz = oz;
                }
            }
            /* broadcast winner to lanes 0..7, each publishes to peer=lane */
            v  = __shfl_sync(0x000000ffu, v, 0, 8);
            i  = __shfl_sync(0x000000ffu, i, 0, 8);
            xx = __shfl_sync(0x000000ffu, xx, 0, 8);
            yy = __shfl_sync(0x000000ffu, yy, 0, 8);
            zz = __shfl_sync(0x000000ffu, zz, 0, 8);
            unsigned pb = peer_gm + (unsigned)((par * 64 + (int)rank * 8) * 4);
            st_clu(pb + 4,  __float_as_int(v));
            st_clu(pb + 8,  i);
            st_clu(pb + 12, __float_as_int(xx));
            st_clu(pb + 16, __float_as_int(yy));
            st_clu(pb + 20, __float_as_int(zz));
            st_rel_clu(pb, it);
        }
        /* all threads: wait for 8 cluster slots, pick global winner */
        {
            float nv = -1.0f, nx = 0.f, ny = 0.f, nz = 0.f;
            int ni = 0x7fffffff;
#pragma unroll
            for (int s = 0; s < 8; s++) {
                unsigned ta = smem_u32(&gm[par][s][0]);
                while (ld_acq_clu(ta) != it) {}
                float v = __int_as_float(gm[par][s][1]);
                int   i = gm[par][s][2];
                if (v > nv || (v == nv && i < ni)) {
                    nv = v; ni = i;
                    nx = __int_as_float(gm[par][s][3]);
                    ny = __int_as_float(gm[par][s][4]);
                    nz = __int_as_float(gm[par][s][5]);
                }
            }
            cx = nx; cy = ny; cz = nz;
        }
    }
}

/* ------------------------------------------------------------------ */
/* KNN top-32, 8-way candidate split (proven bit-exact semantics).     */
/* ------------------------------------------------------------------ */
__global__ __launch_bounds__(256)
void knn_k(const float* __restrict__ xyz) {
    extern __shared__ float ks[];
    float* scx = ks;
    float* scy = ks + NN;
    float* scz = ks + 2 * NN;

    int qg = blockIdx.x * 32;          /* 512 blocks cover 16384 queries */
    int b = qg >> 11;
    const float* x = xyz + (size_t)b * 3 * NN;
    int tid = threadIdx.x;

    for (int i = tid; i < NN; i += 256) {
        scx[i] = x[i];
        scy[i] = x[NN + i];
        scz[i] = x[2 * NN + i];
    }
    __syncthreads();

    int q = tid & 31, s = tid >> 5;
    int qi = qg + q;
    float qx = g_newxyz[qi * 3 + 0];
    float qy = g_newxyz[qi * 3 + 1];
    float qz = g_newxyz[qi * 3 + 2];
    float qq = sq3_dag(qx, qy, qz);

    float kd[KS]; int ki[KS];
#pragma unroll
    for (int j = 0; j < KS; j++) { kd[j] = 3.0e38f; ki[j] = 0; }

    int c0 = s * 2048;
    float worst = kd[KS - 1];
#pragma unroll 4
    for (int i = 0; i < 2048; i++) {
        int c = c0 + i;
        float cxv = scx[c], cyv = scy[c], czv = scz[c];
        float pp = sq3_dag(cxv, cyv, czv);
        float dot = __fmaf_rn(qz, czv, __fmaf_rn(qy, cyv, __fmul_rn(qx, cxv)));
        float d = __fadd_rn(__fmaf_rn(-2.0f, dot, qq), pp);
        if (d < worst) {
            int pos = KS - 1;
            while (pos > 0 && kd[pos - 1] > d) {
                kd[pos] = kd[pos - 1]; ki[pos] = ki[pos - 1]; pos--;
            }
            kd[pos] = d; ki[pos] = c;
            worst = kd[KS - 1];
        }
    }
    __syncthreads();

    float* md = ks;
    int*   mi = (int*)(ks + 8192);
    for (int r = 0; r < KS; r++) {
        md[(q * 8 + s) * 32 + r] = kd[r];
        mi[(q * 8 + s) * 32 + r] = ki[r];
    }
    __syncthreads();

    if (tid < 32) {
        int p8[8] = {0, 0, 0, 0, 0, 0, 0, 0};
        int base = (qg + tid) * KS;
        for (int r = 0; r < KS; r++) {
            float bd = 3.5e38f; int bidx = 0x7fffffff; int bsel = 0;
#pragma unroll
            for (int s2 = 0; s2 < 8; s2++) {
                float d2 = md[(tid * 8 + s2) * 32 + p8[s2]];
                int   i2 = mi[(tid * 8 + s2) * 32 + p8[s2]];
                if (d2 < bd || (d2 == bd && i2 < bidx)) { bd = d2; bidx = i2; bsel = s2; }
            }
            g_knn[base + r] = bidx;
            p8[bsel]++;
        }
    }
}

/* ------------------------------------------------------------------ */
/* Build feat[s][68]: [0:3)=xyz-center, [3:67)=points row, [67]=pad.   */
/* ------------------------------------------------------------------ */
__global__ __launch_bounds__(256)
void feat_k(const float* __restrict__ xyz) {
    int s = blockIdx.x * 8 + (threadIdx.x >> 5);
    int lane = threadIdx.x & 31;
    int b = s >> 16;
    int p = (s >> 5) & (NP - 1);
    int i = g_knn[s];
    const float* pt = g_pointsT + ((size_t)b * NN + i) * 64;
    float* f = g_feat + (size_t)s * LDF;
    for (int c = lane; c < LDF; c += 32) {
        float v;
        if (c < 3)
            v = __fadd_rn(xyz[(size_t)b * 3 * NN + c * NN + i],
                          -g_newxyz[(b * NP + p) * 3 + c]);
        else if (c < 67)
            v = pt[c - 3];
        else
            v = 0.f;
        f[c] = v;
    }
}

/* ------------------------------------------------------------------ */
/* Fused 1x1-conv GEMM, full f32 (proven: rel_err 1.3e-7).             */
/* ------------------------------------------------------------------ */
template<int M, int KIN, int LDB, int SB, int TS, int TC,
         bool INAFF, bool STATS, bool MAXPOOL>
__global__ __launch_bounds__(256)
void gemm_k(const float* __restrict__ Wg, const float* __restrict__ Xg,
            float* __restrict__ Og, const float* __restrict__ bias,
            int affoff, int statoff)
{
    constexpr int NS  = SB / TS;
    constexpr int WST = M + 4;
    constexpr int XST = SB + 4;
    __shared__ __align__(16) float Ws[KIN * WST];
    __shared__ __align__(16) float Xs[KIN * XST];
    int t = threadIdx.x;

    for (int idx = t; idx < M * KIN; idx += 256) {
        int m = idx / KIN, k = idx - m * KIN;
        Ws[k * WST + m] = Wg[idx];
    }
    size_t sbase = (size_t)blockIdx.x * SB;
    for (int idx = t; idx < SB * KIN; idx += 256) {
        int s = idx / KIN, k = idx - s * KIN;
        float v = Xg[(sbase + s) * (size_t)LDB + k];
        if (INAFF)
            v = fmaxf(fmaf(g_aff[affoff + k], v, g_aff[affoff + 64 + k]), 0.f);
        Xs[k * XST + s] = v;
    }
    __syncthreads();

    int s_idx = t % NS, c_idx = t / NS;
    int sj = s_idx * TS, cj = c_idx * TC;
    float acc[TS][TC];
#pragma unroll
    for (int i = 0; i < TS; i++)
#pragma unroll
        for (int j = 0; j < TC; j++) acc[i][j] = 0.f;

    for (int k = 0; k < KIN; k++) {
        float xs[TS], wv[TC];
#pragma unroll
        for (int i = 0; i < TS; i++) xs[i] = Xs[k * XST + sj + i];
#pragma unroll
        for (int j = 0; j < TC; j++) wv[j] = Ws[k * WST + cj + j];
#pragma unroll
        for (int i = 0; i < TS; i++)
#pragma unroll
            for (int j = 0; j < TC; j++)
                acc[i][j] = fmaf(xs[i], wv[j], acc[i][j]);
    }

    if (MAXPOOL) {
        int b = (int)(sbase >> 16);
        int p = (int)((sbase >> 5) & (NP - 1));
#pragma unroll
        for (int j = 0; j < TC; j++) {
            float m = acc[0][j];
#pragma unroll
            for (int i = 1; i < TS; i++) m = fmaxf(m, acc[i][j]);
#pragma unroll
            for (int off = NS / 2; off > 0; off >>= 1)
                m = fmaxf(m, __shfl_xor_sync(0xffffffffu, m, off));
            if (s_idx == 0)
                Og[(size_t)(b * 128 + cj + j) * NP + p] = m + bias[cj + j];
        }
    } else {
#pragma unroll
        for (int i = 0; i < TS; i++)
#pragma unroll
            for (int j = 0; j < TC; j++)
                Og[(sbase + sj + i) * 64 + cj + j] = acc[i][j];
    }

    if (STATS) {
#pragma unroll
        for (int j = 0; j < TC; j++) {
            double s1 = 0.0, s2 = 0.0;
#pragma unroll
            for (int i = 0; i < TS; i++) {
                double v = (double)acc[i][j]; s1 += v; s2 += v * v;
            }
#pragma unroll
            for (int off = NS / 2; off > 0; off >>= 1) {
                s1 += __shfl_xor_sync(0xffffffffu, s1, off);
                s2 += __shfl_xor_sync(0xffffffffu, s2, off);
            }
            if (s_idx == 0) {
                atomicAdd(&g_stats[statoff + cj + j], s1);
                atomicAdd(&g_stats[statoff + 64 + cj + j], s2);
            }
        }
    }
}

/* BN fold: scale = gamma/sqrt(var+eps), shift = beta - mean*scale */
__global__ void fold_k(const float* __restrict__ gamma, const float* __restrict__ beta,
                       int statoff, int affoff) {
    int c = threadIdx.x;
    if (c >= 64) return;
    double n = (double)SFULL;
    double mean = g_stats[statoff + c] / n;
    double var = g_stats[statoff + 64 + c] / n - mean * mean;
    double sc = (double)gamma[c] / sqrt(var + 1e-5);
    g_aff[affoff + c] = (float)sc;
    g_aff[affoff + 64 + c] = (float)((double)beta[c] - mean * sc);
}

/* ------------------------------------------------------------------ */
extern "C" void kernel_launch(void* const* d_in, const int* in_sizes, int n_in,
                              void* d_out, int out_size) {
    const float* xyz    = (const float*)d_in[0];
    const float* points = (const float*)d_in[1];
    const float* W0  = (const float*)d_in[2];
    const float* g0  = (const float*)d_in[4];
    const float* bt0 = (const float*)d_in[5];
    const float* W1  = (const float*)d_in[6];
    const float* g1  = (const float*)d_in[8];
    const float* bt1 = (const float*)d_in[9];
    const float* W2  = (const float*)d_in[10];
    const float* b2  = (const float*)d_in[11];
    float* out    = (float*)d_out;
    float* out_np = out + BB * 3 * NP;     /* new_points after new_xyz */

    void* p_feat = 0; void* p_h0 = 0;
    cudaGetSymbolAddress(&p_feat, g_feat);
    cudaGetSymbolAddress(&p_h0, g_h0);
    float* feat = (float*)p_feat;
    float* h0   = (float*)p_h0;

    const int knn_smem = 3 * NN * 4;   /* 192KB */
    cudaFuncSetAttribute(knn_k, cudaFuncAttributeMaxDynamicSharedMemorySize, knn_smem);

    zero_stats_k<<<1, 256>>>();
    transpose_k<<<dim3(NN / 32, 2, BB), dim3(32, 8)>>>(points);
    fps_k<<<BB * CL, 256>>>(xyz, out);            /* cluster-8, poll-based */
    knn_k<<<512, 256, knn_smem>>>(xyz);
    feat_k<<<SFULL / 8, 256>>>(xyz);

    /* L0: 67 -> 64, raw output + stats */
    gemm_k<64, 67, 68, 64, 4, 4, false, true, false>
        <<<SFULL / 64, 256>>>(W0, feat, h0, nullptr, 0, 0);
    fold_k<<<1, 64>>>(g0, bt0, 0, 0);
    /* L1: relu(BN(h0)) -> 64, raw output + stats (h1 stored into feat) */
    gemm_k<64, 64, 64, 64, 4, 4, true, true, false>
        <<<SFULL / 64, 256>>>(W1, h0, feat, nullptr, 0, 128);
    fold_k<<<1, 64>>>(g1, bt1, 128, 128);
    /* L2: relu(BN(h1)) -> 128, fused max over k, +b2 */
    gemm_k<128, 64, 64, 32, 2, 8, true, false, true>
        <<<SFULL / 32, 256>>>(W2, feat, out_np, b2, 128, 0);
}